// round 2
// baseline (speedup 1.0000x reference)
#include <cuda_runtime.h>
#include <cuda_bf16.h>

// Problem constants
#define BATCH   8
#define IN_P    16     // in_planes
#define REP_C   16     // PROD_DW / IN_PLANES
#define OUT_P   32     // out_planes
#define HW      1024   // 32*32
#define PV      256    // HW / 4 (float4 pixel-vecs)
#define C_X     256    // PROD_DW channels of x
#define C_OUT1  8192   // OUT_P * PROD_DW

// out1 element count = 8*8192*1024 = 67108864 ; out2 follows it in d_out.
#define OUT1_VECS ((size_t)BATCH * C_OUT1 * PV)   // 16777216 float4

__global__ __launch_bounds__(256) void qconv_pw_kernel(
    const float4* __restrict__ x,      // (B, 256, 1024) as float4: (B,256,256)
    const float4* __restrict__ x2,     // (B, 16, 1024)  as float4: (B,16,256)
    const float*  __restrict__ w,      // (32,16) flattened from (512,1,1,1)
    float4* __restrict__ out)          // out1 vecs then out2 vecs
{
    const int blk = blockIdx.x;        // 0..1023
    const int iq  = blk & 3;           // i-quarter (4 i values each)
    const int o   = (blk >> 2) & 31;
    const int b   = blk >> 7;
    const int p   = threadIdx.x;       // pixel-vec 0..255

    __shared__ float ws[IN_P];
    if (threadIdx.x < IN_P) ws[threadIdx.x] = w[o * IN_P + threadIdx.x];
    __syncthreads();

    const float4* xb   = x   + (size_t)b * C_X * PV + p;
    float4*       out1 = out + ((size_t)b * C_OUT1 + (size_t)o * 256) * PV + p;

    #pragma unroll
    for (int ii = 0; ii < 4; ii++) {
        const int i = iq * 4 + ii;
        const float wv = ws[i];

        // Load the 16 rep-channels for this (b,i) pixel-vec; keep in registers.
        float4 xr[REP_C];
        const float4* xc = xb + (size_t)(i * REP_C) * PV;
        #pragma unroll
        for (int r = 0; r < REP_C; r++)
            xr[r] = __ldg(&xc[(size_t)r * PV]);

        // Reference sums the PRODUCTS w*x_r (out1 then segment-sum) -> match
        // that rounding order for the threshold.
        float tx = 0.f, ty = 0.f, tz = 0.f, tw = 0.f;
        #pragma unroll
        for (int r = 0; r < REP_C; r++) {
            tx += wv * xr[r].x;
            ty += wv * xr[r].y;
            tz += wv * xr[r].z;
            tw += wv * xr[r].w;
        }

        float4 g;
        g.x = (tx > 0.f) ? wv : 0.f;
        g.y = (ty > 0.f) ? wv : 0.f;
        g.z = (tz > 0.f) ? wv : 0.f;
        g.w = (tw > 0.f) ? wv : 0.f;

        float4* dst = out1 + (size_t)(i * REP_C) * PV;
        #pragma unroll
        for (int r = 0; r < REP_C; r++) {
            float4 v;
            v.x = g.x * xr[r].x;
            v.y = g.y * xr[r].y;
            v.z = g.z * xr[r].z;
            v.w = g.w * xr[r].w;
            __stcs(&dst[(size_t)r * PV], v);   // streaming: don't pollute L2
        }
    }

    // Dense 1x1 conv + ReLU path (tiny). One i-quarter subset of blocks does it.
    if (iq == 0) {
        const float4* x2b = x2 + (size_t)b * IN_P * PV + p;
        float ax = 0.f, ay = 0.f, az = 0.f, aw = 0.f;
        #pragma unroll
        for (int i = 0; i < IN_P; i++) {
            const float4 v = __ldg(&x2b[(size_t)i * PV]);
            const float wv = ws[i];
            ax = fmaf(wv, v.x, ax);
            ay = fmaf(wv, v.y, ay);
            az = fmaf(wv, v.z, az);
            aw = fmaf(wv, v.w, aw);
        }
        float4 r;
        r.x = fmaxf(ax, 0.f);
        r.y = fmaxf(ay, 0.f);
        r.z = fmaxf(az, 0.f);
        r.w = fmaxf(aw, 0.f);
        out[OUT1_VECS + ((size_t)b * OUT_P + o) * PV + p] = r;
    }
}

extern "C" void kernel_launch(void* const* d_in, const int* in_sizes, int n_in,
                              void* d_out, int out_size)
{
    const float4* x  = (const float4*)d_in[0];   // (8,256,32,32) fp32
    const float4* x2 = (const float4*)d_in[1];   // (8,16,32,32)  fp32
    const float*  w  = (const float*) d_in[2];   // (512,1,1,1)   fp32
    float4* out = (float4*)d_out;

    qconv_pw_kernel<<<BATCH * OUT_P * 4, 256>>>(x, x2, w, out);
}